// round 15
// baseline (speedup 1.0000x reference)
#include <cuda_runtime.h>
#include <cuda_fp16.h>
#include <math.h>
#include <stdint.h>

#define C_     32
#define NC_    2000
#define N_     10000
#define E_     30000
#define D_     128
#define L_     4
#define F_FEAT 140
#define F_CFG  18
#define F_EMB  4
#define NT_    79
#define TILES2_ (C_ * NT_)              // 2528
#define GEMM_CTAS 304

// ---------------- scratch ----------------
__device__ __half g_xh  [(size_t)C_ * N_ * D_];   // activations, fp16
__device__ __half g_aggh[(size_t)C_ * N_ * D_];   // aggregated means, fp16
__device__ float  g_base[(size_t)N_ * D_];
__device__ int    g_cnt [N_];
__device__ int    g_fill[N_];
__device__ int    g_indptr[N_ + 1];
__device__ int    g_csr[E_];
__device__ float  g_pool[C_ * D_];
__device__ __half g_Bh  [(size_t)L_ * 128 * 256]; // fp16 weights [l][n][k]

// ================= mma.sync helpers =================
__device__ __forceinline__ uint32_t smem_u32(const void* p) {
    uint32_t a;
    asm("{ .reg .u64 t; cvta.to.shared.u64 t, %1; cvt.u32.u64 %0, t; }" : "=r"(a) : "l"(p));
    return a;
}
__device__ __forceinline__ void ldsm_x4(uint32_t* r, uint32_t addr) {
    asm volatile("ldmatrix.sync.aligned.m8n8.x4.shared.b16 {%0,%1,%2,%3}, [%4];"
                 : "=r"(r[0]), "=r"(r[1]), "=r"(r[2]), "=r"(r[3]) : "r"(addr));
}
__device__ __forceinline__ void mma16816(float* c, const uint32_t* a, const uint32_t* b) {
    asm volatile("mma.sync.aligned.m16n8k16.row.col.f32.f16.f16.f32 "
                 "{%0,%1,%2,%3}, {%4,%5,%6,%7}, {%8,%9}, {%0,%1,%2,%3};"
                 : "+f"(c[0]), "+f"(c[1]), "+f"(c[2]), "+f"(c[3])
                 : "r"(a[0]), "r"(a[1]), "r"(a[2]), "r"(a[3]), "r"(b[0]), "r"(b[1]));
}

// ---------------- launch 1: edge count + input projection ----------------
__global__ void k_count_base(const float* __restrict__ x_feat, const int* __restrict__ x_op,
                             const float* __restrict__ emb, const float* __restrict__ W_lin,
                             const float* __restrict__ b_lin, const int* __restrict__ dst,
                             int E) {
    int bx = blockIdx.x;
    int tid = threadIdx.x;
    if (bx >= 625) {
        int e = (bx - 625) * 128 + tid;
        if (e < E) atomicAdd(&g_cnt[dst[e]], 1);
        return;
    }
    __shared__ float s_in[16][F_FEAT + F_EMB];
    int n0 = bx * 16;
    for (int i = tid; i < 16 * F_FEAT; i += 128) {
        int m = i / F_FEAT, k = i % F_FEAT;
        s_in[m][k] = x_feat[(size_t)(n0 + m) * F_FEAT + k];
    }
    if (tid < 16 * F_EMB) {
        int m = tid / F_EMB, k = tid % F_EMB;
        s_in[m][F_FEAT + k] = emb[x_op[n0 + m] * F_EMB + k];
    }
    __syncthreads();
    float b = b_lin[tid];
#pragma unroll
    for (int k = 0; k < F_CFG; k++) b -= 2.0f * W_lin[(F_FEAT + k) * D_ + tid];
    float acc[16];
#pragma unroll
    for (int m = 0; m < 16; m++) acc[m] = b;
    const float* Wc = W_lin + tid;
#pragma unroll 4
    for (int k = 0; k < F_FEAT; k++) {
        float w = Wc[k * D_];
#pragma unroll
        for (int m = 0; m < 16; m++) acc[m] += s_in[m][k] * w;
    }
#pragma unroll
    for (int k = 0; k < F_EMB; k++) {
        float w = Wc[(F_FEAT + F_CFG + k) * D_];
#pragma unroll
        for (int m = 0; m < 16; m++) acc[m] += s_in[m][F_FEAT + k] * w;
    }
#pragma unroll
    for (int m = 0; m < 16; m++) g_base[(size_t)(n0 + m) * D_ + tid] = acc[m];
}

// ---------------- launch 2: scan (block 0) + fp16 broadcast + weight cvt ----------
__global__ void __launch_bounds__(1024) k_scan_bcast_wt(const float* __restrict__ Wl,
                                                        const float* __restrict__ Wr) {
    int t = threadIdx.x;
    int bx = blockIdx.x;
    if (bx == 0) {
        const int CH = 10;
#pragma unroll
        for (int q = 0; q < 4; q++) g_pool[q * 1024 + t] = 0.f;
        int base = t * CH;
        int vals[CH];
        int s = 0;
#pragma unroll
        for (int i = 0; i < CH; i++) {
            int idx = base + i;
            int v = (idx < N_) ? g_cnt[idx] : 0;
            if (idx < N_) { g_cnt[idx] = 0; g_fill[idx] = 0; }
            vals[i] = v; s += v;
        }
        int lane = t & 31, wid = t >> 5;
        int inc = s;
#pragma unroll
        for (int o = 1; o < 32; o <<= 1) {
            int y = __shfl_up_sync(0xffffffffu, inc, o);
            if (lane >= o) inc += y;
        }
        __shared__ int wtot[32];
        if (lane == 31) wtot[wid] = inc;
        __syncthreads();
        if (wid == 0) {
            int v = wtot[lane];
#pragma unroll
            for (int o = 1; o < 32; o <<= 1) {
                int y = __shfl_up_sync(0xffffffffu, v, o);
                if (lane >= o) v += y;
            }
            wtot[lane] = v;
        }
        __syncthreads();
        int excl = inc - s + (wid > 0 ? wtot[wid - 1] : 0);
        int run = excl;
#pragma unroll
        for (int i = 0; i < CH; i++) {
            int idx = base + i;
            if (idx < N_) g_indptr[idx] = run;
            run += vals[i];
        }
        if (t == 1023) g_indptr[N_] = run;
        return;
    }
    if (bx <= 10000) {                                // fp16 broadcast
        size_t i = (size_t)(bx - 1) * 1024 + t;
        size_t c = i / (N_ * 32);
        size_t r = i - c * (N_ * 32);
        float4 v = ((const float4*)g_base)[r];
        uint2 uh;
        __half2 h01 = __floats2half2_rn(v.x, v.y);
        __half2 h23 = __floats2half2_rn(v.z, v.w);
        uh.x = *(uint32_t*)&h01; uh.y = *(uint32_t*)&h23;
        ((uint2*)g_xh)[c * ((size_t)N_ * 32) + r] = uh;
        return;
    }
    int idx = (bx - 10001) * 1024 + t;                // weight convert (128 blocks)
    int l = idx >> 15;
    int rem = idx & 32767;
    int n = rem >> 8, k = rem & 255;
    float v = (k < 128) ? Wl[((size_t)l * 128 + k) * 128 + n]
                        : Wr[((size_t)l * 128 + (k - 128)) * 128 + n];
    g_Bh[idx] = __float2half_rn(v);
}

// ---------------- launch 3: config correction (block per node) + CSR fill ----------
__global__ void __launch_bounds__(256) k_correct_fill(
        const float* __restrict__ xcfg, const int* __restrict__ nid,
        const float* __restrict__ W_lin,
        const int* __restrict__ src, const int* __restrict__ dst, int E) {
    int bx = blockIdx.x;
    int tid = threadIdx.x;
    if (bx >= NC_) {                                  // fill part
        int e = (bx - NC_) * 256 + tid;
        if (e < E) {
            int d = dst[e];
            int pos = g_indptr[d] + atomicAdd(&g_fill[d], 1);
            g_csr[pos] = src[e];
        }
        return;
    }
    int j = bx;
    int n = nid[j];
    if (j < NC_ - 1 && nid[j + 1] == n) return;       // last-occurrence-wins
    __shared__ float sW[F_CFG][128];
    __shared__ float sC[C_][F_CFG];
    __shared__ float sB[128];
    for (int i = tid; i < F_CFG * 128; i += 256)
        sW[i >> 7][i & 127] = W_lin[(F_FEAT + (i >> 7)) * D_ + (i & 127)];
    for (int i = tid; i < C_ * F_CFG; i += 256)
        sC[i / F_CFG][i % F_CFG] =
            xcfg[((size_t)(i / F_CFG) * NC_ + j) * F_CFG + (i % F_CFG)] + 2.0f;
    if (tid < 128) sB[tid] = g_base[(size_t)n * D_ + tid];
    __syncthreads();
#pragma unroll
    for (int r = 0; r < 16; r++) {
        int i = r * 256 + tid;
        int c = i >> 7, col = i & 127;
        float acc = sB[col];
#pragma unroll
        for (int k = 0; k < F_CFG; k++) acc += sC[c][k] * sW[k][col];
        g_xh[((size_t)c * N_ + n) * D_ + col] = __float2half_rn(acc);
    }
}

// ---------------- propagation: warp per (c,n); half-warps take even/odd edges ------
__global__ void k_prop() {
    int gw = (blockIdx.x * blockDim.x + threadIdx.x) >> 5;
    int lane = threadIdx.x & 31;
    if (gw >= C_ * N_) return;
    int c = gw / N_, n = gw - c * N_;
    int beg = g_indptr[n], end = g_indptr[n + 1];
    const size_t cbase = (size_t)c * N_;
    const int half = lane >> 4, li = lane & 15;
    float a0 = 0.f, a1 = 0.f, a2 = 0.f, a3 = 0.f;
    float a4 = 0.f, a5 = 0.f, a6 = 0.f, a7 = 0.f;
    for (int e = beg + half; e < end; e += 2) {
        int src = g_csr[e];
        uint4 u = *(const uint4*)(g_xh + (cbase + src) * D_ + li * 8);
        float2 f0 = __half22float2(*(__half2*)&u.x);
        float2 f1 = __half22float2(*(__half2*)&u.y);
        float2 f2 = __half22float2(*(__half2*)&u.z);
        float2 f3 = __half22float2(*(__half2*)&u.w);
        a0 += f0.x; a1 += f0.y; a2 += f1.x; a3 += f1.y;
        a4 += f2.x; a5 += f2.y; a6 += f3.x; a7 += f3.y;
    }
    a0 += __shfl_xor_sync(0xffffffffu, a0, 16);
    a1 += __shfl_xor_sync(0xffffffffu, a1, 16);
    a2 += __shfl_xor_sync(0xffffffffu, a2, 16);
    a3 += __shfl_xor_sync(0xffffffffu, a3, 16);
    a4 += __shfl_xor_sync(0xffffffffu, a4, 16);
    a5 += __shfl_xor_sync(0xffffffffu, a5, 16);
    a6 += __shfl_xor_sync(0xffffffffu, a6, 16);
    a7 += __shfl_xor_sync(0xffffffffu, a7, 16);
    if (half == 0) {
        float inv = 1.0f / fmaxf((float)(end - beg), 1.0f);
        uint4 o;
        __half2 h0 = __floats2half2_rn(a0 * inv, a1 * inv);
        __half2 h1 = __floats2half2_rn(a2 * inv, a3 * inv);
        __half2 h2 = __floats2half2_rn(a4 * inv, a5 * inv);
        __half2 h3 = __floats2half2_rn(a6 * inv, a7 * inv);
        o.x = *(uint32_t*)&h0; o.y = *(uint32_t*)&h1;
        o.z = *(uint32_t*)&h2; o.w = *(uint32_t*)&h3;
        *(uint4*)(g_aggh + (cbase + n) * D_ + li * 8) = o;
    }
}

// ---------------- mma.sync dual GEMM (R14: 2 CTAs/SM) ----------------
#define ASTRIDE_B 144
#define PLANE_B   18432
#define B_BYTES   (4 * PLANE_B)          // 73728
#define A_BYTES   (2 * PLANE_B)          // 36864
#define SMEM_GEMM (B_BYTES + A_BYTES)    // 110592

template <bool LAST>
__global__ void __launch_bounds__(256, 2) k_gemm(const float* __restrict__ conv_b,
                                                 int layer) {
    extern __shared__ __align__(16) char sm[];
    char* Bsm = sm;
    char* Asm = sm + B_BYTES;
    __shared__ float s_bias[128];

    const int tid = threadIdx.x;
    const int lane = tid & 31;
    const int wid = tid >> 5;
    const int wm = wid >> 2;
    const int wn = wid & 3;
    const int m0 = wm * 64, n0 = wn * 32;

    if (tid < 128) s_bias[tid] = conv_b[(size_t)layer * D_ + tid];

    // B copy: fp16 plane, pure uint4 copy (4096 slots)
    {
        const __half* Bh = g_Bh + (size_t)layer * 32768;
#pragma unroll
        for (int i = 0; i < 16; i++) {
            int slot = i * 256 + tid;
            int chunk = slot >> 10;
            int n = (slot >> 3) & 127, q = slot & 7;
            const __half* src = Bh + (size_t)n * 256 + chunk * 64 + q * 8;
            *(uint4*)(Bsm + chunk * PLANE_B + n * ASTRIDE_B + q * 16) = *(const uint4*)src;
        }
    }
    __syncthreads();

    const uint32_t a_u32 = smem_u32(Asm);
    const uint32_t b_u32 = smem_u32(Bsm);

    for (int t = blockIdx.x; t < TILES2_; t += gridDim.x) {
        const int cfg = t / NT_;
        const int nt = t - cfg * NT_;
        const int nvalid = (nt == NT_ - 1) ? (N_ - 128 * (NT_ - 1)) : 128;
        const size_t row0 = (size_t)cfg * N_ + (size_t)nt * 128;

        float acc[4][4][4];
#pragma unroll
        for (int mi = 0; mi < 4; mi++)
#pragma unroll
            for (int ni = 0; ni < 4; ni++)
#pragma unroll
                for (int q = 0; q < 4; q++) acc[mi][ni][q] = 0.f;

        uint4 av[4];
        {
#pragma unroll
            for (int i = 0; i < 4; i++) {
                int slot = i * 256 + tid;
                int n = slot >> 3, q = slot & 7;
                int nc = n < nvalid ? n : nvalid - 1;
                av[i] = *(const uint4*)(g_aggh + (row0 + nc) * 128 + q * 8);
            }
#pragma unroll
            for (int i = 0; i < 4; i++) {
                int slot = i * 256 + tid;
                int n = slot >> 3, q = slot & 7;
                *(uint4*)(Asm + n * ASTRIDE_B + q * 16) = av[i];
            }
        }
        __syncthreads();

#pragma unroll 1
        for (int s = 0; s < 4; s++) {
            if (s < 3) {
                const int koff = ((s + 1) & 1) * 64;
                const __half* srcp = ((s + 1) < 2) ? g_aggh : g_xh;
#pragma unroll
                for (int i = 0; i < 4; i++) {
                    int slot = i * 256 + tid;
                    int n = slot >> 3, q = slot & 7;
                    int nc = n < nvalid ? n : nvalid - 1;
                    av[i] = *(const uint4*)(srcp + (row0 + nc) * 128 + koff + q * 8);
                }
            }

            const uint32_t abase = a_u32 + (s & 1) * PLANE_B;
            const uint32_t bbase = b_u32 + s * PLANE_B;
#pragma unroll
            for (int ks = 0; ks < 4; ks++) {
                const int kofs = ks * 16;
                uint32_t ah[4][4], bh[4][2];
#pragma unroll
                for (int mi = 0; mi < 4; mi++) {
                    uint32_t addr = abase + (uint32_t)(m0 + mi * 16 + (lane & 15)) * ASTRIDE_B
                                  + (uint32_t)(kofs + (lane >> 4) * 8) * 2;
                    ldsm_x4(ah[mi], addr);
                }
#pragma unroll
                for (int np = 0; np < 2; np++) {
                    uint32_t addr = bbase + (uint32_t)(n0 + np * 16 + (lane & 15)) * ASTRIDE_B
                                  + (uint32_t)(kofs + (lane >> 4) * 8) * 2;
                    uint32_t bq[4];
                    ldsm_x4(bq, addr);
                    bh[np * 2][0] = bq[0]; bh[np * 2][1] = bq[2];
                    bh[np * 2 + 1][0] = bq[1]; bh[np * 2 + 1][1] = bq[3];
                }
#pragma unroll
                for (int mi = 0; mi < 4; mi++)
#pragma unroll
                    for (int ni = 0; ni < 4; ni++)
                        mma16816(acc[mi][ni], ah[mi], bh[ni]);
            }

            if (s < 3) {
                __syncthreads();
                const int b = (s + 1) & 1;
#pragma unroll
                for (int i = 0; i < 4; i++) {
                    int slot = i * 256 + tid;
                    int n = slot >> 3, q = slot & 7;
                    *(uint4*)(Asm + b * PLANE_B + n * ASTRIDE_B + q * 16) = av[i];
                }
                __syncthreads();
            }
        }

        if (!LAST) {
#pragma unroll
            for (int mi = 0; mi < 4; mi++) {
                int rr = m0 + mi * 16 + (lane >> 2);
                bool v0 = rr < nvalid, v1 = rr + 8 < nvalid;
                size_t r0 = row0 + rr;
                size_t r1 = r0 + 8;
#pragma unroll
                for (int ni = 0; ni < 4; ni++) {
                    int col = n0 + ni * 8 + (lane & 3) * 2;
                    float b0 = s_bias[col], b1 = s_bias[col + 1];
                    __half2 o0 = __floats2half2_rn(fmaxf(acc[mi][ni][0] + b0, 0.f),
                                                   fmaxf(acc[mi][ni][1] + b1, 0.f));
                    __half2 o1 = __floats2half2_rn(fmaxf(acc[mi][ni][2] + b0, 0.f),
                                                   fmaxf(acc[mi][ni][3] + b1, 0.f));
                    if (v0) *(uint32_t*)(g_xh + r0 * 128 + col) = *(uint32_t*)&o0;
                    if (v1) *(uint32_t*)(g_xh + r1 * 128 + col) = *(uint32_t*)&o1;
                }
            }
        } else {
            float p[4][2];
#pragma unroll
            for (int ni = 0; ni < 4; ni++) { p[ni][0] = 0.f; p[ni][1] = 0.f; }
#pragma unroll
            for (int mi = 0; mi < 4; mi++) {
                int rr = m0 + mi * 16 + (lane >> 2);
                float v0 = (rr < nvalid) ? 1.f : 0.f;
                float v1 = (rr + 8 < nvalid) ? 1.f : 0.f;
#pragma unroll
                for (int ni = 0; ni < 4; ni++) {
                    int col = n0 + ni * 8 + (lane & 3) * 2;
                    float b0 = s_bias[col], b1 = s_bias[col + 1];
                    p[ni][0] += v0 * fmaxf(acc[mi][ni][0] + b0, 0.f)
                              + v1 * fmaxf(acc[mi][ni][2] + b0, 0.f);
                    p[ni][1] += v0 * fmaxf(acc[mi][ni][1] + b1, 0.f)
                              + v1 * fmaxf(acc[mi][ni][3] + b1, 0.f);
                }
            }
#pragma unroll
            for (int ni = 0; ni < 4; ni++)
#pragma unroll
                for (int h = 0; h < 2; h++) {
#pragma unroll
                    for (int o = 4; o <= 16; o <<= 1)
                        p[ni][h] += __shfl_xor_sync(0xffffffffu, p[ni][h], o);
                }
            if (lane < 4) {
#pragma unroll
                for (int ni = 0; ni < 4; ni++) {
                    int col = n0 + ni * 8 + lane * 2;
                    atomicAdd(&g_pool[cfg * 128 + col], p[ni][0]);
                    atomicAdd(&g_pool[cfg * 128 + col + 1], p[ni][1]);
                }
            }
        }
        __syncthreads();
    }
}

// ---------------- MLP head ----------------
__global__ void __launch_bounds__(1024) k_mlp(
        const float* __restrict__ Wd1, const float* __restrict__ bd1,
        const float* __restrict__ Wd2, const float* __restrict__ bd2,
        const float* __restrict__ Wd3, const float* __restrict__ bd3,
        float* __restrict__ out) {
    __shared__ float sa[C_][D_];
    __shared__ float sb[C_][D_];
    int tid = threadIdx.x;
#pragma unroll
    for (int r = 0; r < 4; r++) {
        int i = r * 1024 + tid;
        sa[i >> 7][i & 127] = g_pool[i] * (1.0f / N_);
    }
    __syncthreads();
#pragma unroll
    for (int r = 0; r < 4; r++) {
        int i = r * 1024 + tid;
        int c = i >> 7, j = i & 127;
        float a = bd1[j];
#pragma unroll 8
        for (int k = 0; k < D_; k++) a += sa[c][k] * Wd1[k * D_ + j];
        sb[c][j] = fmaxf(a, 0.f);
    }
    __syncthreads();
#pragma unroll
    for (int r = 0; r < 4; r++) {
        int i = r * 1024 + tid;
        int c = i >> 7, j = i & 127;
        float a = bd2[j];
#pragma unroll 8
        for (int k = 0; k < D_; k++) a += sb[c][k] * Wd2[k * D_ + j];
        sa[c][j] = fmaxf(a, 0.f);
    }
    __syncthreads();
    if (tid < C_) {
        float a = bd3[0];
#pragma unroll 8
        for (int k = 0; k < D_; k++) a += sa[tid][k] * Wd3[k];
        out[tid] = a;
    }
}

// ---------------- launch ----------------
extern "C" void kernel_launch(void* const* d_in, const int* in_sizes, int n_in,
                              void* d_out, int out_size) {
    (void)n_in; (void)out_size;
    const float* x_node_cfg      = (const float*)d_in[0];
    const float* x_feat          = (const float*)d_in[1];
    const int*   x_op            = (const int*)d_in[2];
    const int*   edge_index      = (const int*)d_in[3];
    const int*   node_config_ids = (const int*)d_in[4];
    const float* emb_table       = (const float*)d_in[5];
    const float* W_lin           = (const float*)d_in[6];
    const float* b_lin           = (const float*)d_in[7];
    const float* conv_Wl         = (const float*)d_in[8];
    const float* conv_Wr         = (const float*)d_in[9];
    const float* conv_b          = (const float*)d_in[10];
    const float* Wd1             = (const float*)d_in[11];
    const float* bd1             = (const float*)d_in[12];
    const float* Wd2             = (const float*)d_in[13];
    const float* bd2             = (const float*)d_in[14];
    const float* Wd3             = (const float*)d_in[15];
    const float* bd3             = (const float*)d_in[16];
    float* out = (float*)d_out;

    int E = in_sizes[3] / 2;
    const int* e_src = edge_index;
    const int* e_dst = edge_index + E;

    cudaFuncSetAttribute(k_gemm<false>, cudaFuncAttributeMaxDynamicSharedMemorySize, SMEM_GEMM);
    cudaFuncSetAttribute(k_gemm<true>,  cudaFuncAttributeMaxDynamicSharedMemorySize, SMEM_GEMM);

    int cntBlocks = (E + 127) / 128;
    k_count_base<<<625 + cntBlocks, 128>>>(x_feat, x_op, emb_table, W_lin, b_lin, e_dst, E);
    k_scan_bcast_wt<<<1 + 10000 + 128, 1024>>>(conv_Wl, conv_Wr);
    k_correct_fill<<<NC_ + (E + 255) / 256, 256>>>(x_node_cfg, node_config_ids, W_lin,
                                                   e_src, e_dst, E);

    for (int l = 0; l < L_; l++) {
        k_prop<<<(C_ * N_) / 8, 256>>>();
        if (l < L_ - 1)
            k_gemm<false><<<GEMM_CTAS, 256, SMEM_GEMM>>>(conv_b, l);
        else
            k_gemm<true><<<GEMM_CTAS, 256, SMEM_GEMM>>>(conv_b, l);
    }

    k_mlp<<<1, 1024>>>(Wd1, bd1, Wd2, bd2, Wd3, bd3, out);
}

// round 16
// speedup vs baseline: 1.1558x; 1.1558x over previous
#include <cuda_runtime.h>
#include <cuda_fp16.h>
#include <math.h>
#include <stdint.h>

#define C_     32
#define NC_    2000
#define N_     10000
#define E_     30000
#define D_     128
#define L_     4
#define F_FEAT 140
#define F_CFG  18
#define F_EMB  4
#define NT_    79
#define TILES2_ (C_ * NT_)              // 2528
#define GEMM_CTAS 304

// ---------------- scratch ----------------
__device__ __half g_xh  [(size_t)C_ * N_ * D_];   // activations, fp16
__device__ __half g_aggh[(size_t)C_ * N_ * D_];   // aggregated means, fp16
__device__ float  g_base[(size_t)N_ * D_];
__device__ int    g_cnt [N_];
__device__ int    g_fill[N_];
__device__ int    g_indptr[N_ + 1];
__device__ int    g_csr[E_];
__device__ float  g_pool[C_ * D_];
__device__ __half g_Bh  [(size_t)L_ * 128 * 256]; // fp16 weights [l][n][k]

// ================= mma.sync helpers =================
__device__ __forceinline__ uint32_t smem_u32(const void* p) {
    uint32_t a;
    asm("{ .reg .u64 t; cvta.to.shared.u64 t, %1; cvt.u32.u64 %0, t; }" : "=r"(a) : "l"(p));
    return a;
}
__device__ __forceinline__ void ldsm_x4(uint32_t* r, uint32_t addr) {
    asm volatile("ldmatrix.sync.aligned.m8n8.x4.shared.b16 {%0,%1,%2,%3}, [%4];"
                 : "=r"(r[0]), "=r"(r[1]), "=r"(r[2]), "=r"(r[3]) : "r"(addr));
}
__device__ __forceinline__ void mma16816(float* c, const uint32_t* a, const uint32_t* b) {
    asm volatile("mma.sync.aligned.m16n8k16.row.col.f32.f16.f16.f32 "
                 "{%0,%1,%2,%3}, {%4,%5,%6,%7}, {%8,%9}, {%0,%1,%2,%3};"
                 : "+f"(c[0]), "+f"(c[1]), "+f"(c[2]), "+f"(c[3])
                 : "r"(a[0]), "r"(a[1]), "r"(a[2]), "r"(a[3]), "r"(b[0]), "r"(b[1]));
}

// ---------------- launch 1: edge count + input projection ----------------
__global__ void k_count_base(const float* __restrict__ x_feat, const int* __restrict__ x_op,
                             const float* __restrict__ emb, const float* __restrict__ W_lin,
                             const float* __restrict__ b_lin, const int* __restrict__ dst,
                             int E) {
    int bx = blockIdx.x;
    int tid = threadIdx.x;
    if (bx >= 625) {
        int e = (bx - 625) * 128 + tid;
        if (e < E) atomicAdd(&g_cnt[dst[e]], 1);
        return;
    }
    __shared__ float s_in[16][F_FEAT + F_EMB];
    int n0 = bx * 16;
    for (int i = tid; i < 16 * F_FEAT; i += 128) {
        int m = i / F_FEAT, k = i % F_FEAT;
        s_in[m][k] = x_feat[(size_t)(n0 + m) * F_FEAT + k];
    }
    if (tid < 16 * F_EMB) {
        int m = tid / F_EMB, k = tid % F_EMB;
        s_in[m][F_FEAT + k] = emb[x_op[n0 + m] * F_EMB + k];
    }
    __syncthreads();
    float b = b_lin[tid];
#pragma unroll
    for (int k = 0; k < F_CFG; k++) b -= 2.0f * W_lin[(F_FEAT + k) * D_ + tid];
    float acc[16];
#pragma unroll
    for (int m = 0; m < 16; m++) acc[m] = b;
    const float* Wc = W_lin + tid;
#pragma unroll 4
    for (int k = 0; k < F_FEAT; k++) {
        float w = Wc[k * D_];
#pragma unroll
        for (int m = 0; m < 16; m++) acc[m] += s_in[m][k] * w;
    }
#pragma unroll
    for (int k = 0; k < F_EMB; k++) {
        float w = Wc[(F_FEAT + F_CFG + k) * D_];
#pragma unroll
        for (int m = 0; m < 16; m++) acc[m] += s_in[m][F_FEAT + k] * w;
    }
#pragma unroll
    for (int m = 0; m < 16; m++) g_base[(size_t)(n0 + m) * D_ + tid] = acc[m];
}

// ---------------- launch 2: scan (block 0) + fp16 broadcast + weight cvt ----------
__global__ void __launch_bounds__(1024) k_scan_bcast_wt(const float* __restrict__ Wl,
                                                        const float* __restrict__ Wr) {
    int t = threadIdx.x;
    int bx = blockIdx.x;
    if (bx == 0) {
        const int CH = 10;
#pragma unroll
        for (int q = 0; q < 4; q++) g_pool[q * 1024 + t] = 0.f;
        int base = t * CH;
        int vals[CH];
        int s = 0;
#pragma unroll
        for (int i = 0; i < CH; i++) {
            int idx = base + i;
            int v = (idx < N_) ? g_cnt[idx] : 0;
            if (idx < N_) { g_cnt[idx] = 0; g_fill[idx] = 0; }
            vals[i] = v; s += v;
        }
        int lane = t & 31, wid = t >> 5;
        int inc = s;
#pragma unroll
        for (int o = 1; o < 32; o <<= 1) {
            int y = __shfl_up_sync(0xffffffffu, inc, o);
            if (lane >= o) inc += y;
        }
        __shared__ int wtot[32];
        if (lane == 31) wtot[wid] = inc;
        __syncthreads();
        if (wid == 0) {
            int v = wtot[lane];
#pragma unroll
            for (int o = 1; o < 32; o <<= 1) {
                int y = __shfl_up_sync(0xffffffffu, v, o);
                if (lane >= o) v += y;
            }
            wtot[lane] = v;
        }
        __syncthreads();
        int excl = inc - s + (wid > 0 ? wtot[wid - 1] : 0);
        int run = excl;
#pragma unroll
        for (int i = 0; i < CH; i++) {
            int idx = base + i;
            if (idx < N_) g_indptr[idx] = run;
            run += vals[i];
        }
        if (t == 1023) g_indptr[N_] = run;
        return;
    }
    if (bx <= 10000) {                                // fp16 broadcast
        size_t i = (size_t)(bx - 1) * 1024 + t;
        size_t c = i / (N_ * 32);
        size_t r = i - c * (N_ * 32);
        float4 v = ((const float4*)g_base)[r];
        uint2 uh;
        __half2 h01 = __floats2half2_rn(v.x, v.y);
        __half2 h23 = __floats2half2_rn(v.z, v.w);
        uh.x = *(uint32_t*)&h01; uh.y = *(uint32_t*)&h23;
        ((uint2*)g_xh)[c * ((size_t)N_ * 32) + r] = uh;
        return;
    }
    int idx = (bx - 10001) * 1024 + t;                // weight convert (128 blocks)
    int l = idx >> 15;
    int rem = idx & 32767;
    int n = rem >> 8, k = rem & 255;
    float v = (k < 128) ? Wl[((size_t)l * 128 + k) * 128 + n]
                        : Wr[((size_t)l * 128 + (k - 128)) * 128 + n];
    g_Bh[idx] = __float2half_rn(v);
}

// ---------------- launch 3: config correction (block per node) + CSR fill ----------
__global__ void __launch_bounds__(256) k_correct_fill(
        const float* __restrict__ xcfg, const int* __restrict__ nid,
        const float* __restrict__ W_lin,
        const int* __restrict__ src, const int* __restrict__ dst, int E) {
    int bx = blockIdx.x;
    int tid = threadIdx.x;
    if (bx >= NC_) {                                  // fill part
        int e = (bx - NC_) * 256 + tid;
        if (e < E) {
            int d = dst[e];
            int pos = g_indptr[d] + atomicAdd(&g_fill[d], 1);
            g_csr[pos] = src[e];
        }
        return;
    }
    int j = bx;
    int n = nid[j];
    if (j < NC_ - 1 && nid[j + 1] == n) return;       // last-occurrence-wins
    __shared__ float sW[F_CFG][128];
    __shared__ float sC[C_][F_CFG];
    __shared__ float sB[128];
    for (int i = tid; i < F_CFG * 128; i += 256)
        sW[i >> 7][i & 127] = W_lin[(F_FEAT + (i >> 7)) * D_ + (i & 127)];
    for (int i = tid; i < C_ * F_CFG; i += 256)
        sC[i / F_CFG][i % F_CFG] =
            xcfg[((size_t)(i / F_CFG) * NC_ + j) * F_CFG + (i % F_CFG)] + 2.0f;
    if (tid < 128) sB[tid] = g_base[(size_t)n * D_ + tid];
    __syncthreads();
#pragma unroll
    for (int r = 0; r < 16; r++) {
        int i = r * 256 + tid;
        int c = i >> 7, col = i & 127;
        float acc = sB[col];
#pragma unroll
        for (int k = 0; k < F_CFG; k++) acc += sC[c][k] * sW[k][col];
        g_xh[((size_t)c * N_ + n) * D_ + col] = __float2half_rn(acc);
    }
}

// ---------------- propagation: warp per (config-pair, node) ----------------
// Lanes 0-15 handle config c0, lanes 16-31 handle c0+1. One csr read serves both.
__global__ void k_prop() {
    int gw = (blockIdx.x * blockDim.x + threadIdx.x) >> 5;   // 0 .. 16*N-1
    int lane = threadIdx.x & 31;
    if (gw >= (C_ / 2) * N_) return;
    int cp = gw / N_, n = gw - cp * N_;
    int half = lane >> 4, li = lane & 15;
    int c = cp * 2 + half;
    int beg = g_indptr[n], end = g_indptr[n + 1];
    const __half* xb = g_xh + (size_t)c * N_ * D_ + li * 8;
    float a0 = 0.f, a1 = 0.f, a2 = 0.f, a3 = 0.f;
    float a4 = 0.f, a5 = 0.f, a6 = 0.f, a7 = 0.f;
    for (int e = beg; e < end; e++) {
        int src = g_csr[e];
        uint4 u = *(const uint4*)(xb + (size_t)src * D_);
        float2 f0 = __half22float2(*(__half2*)&u.x);
        float2 f1 = __half22float2(*(__half2*)&u.y);
        float2 f2 = __half22float2(*(__half2*)&u.z);
        float2 f3 = __half22float2(*(__half2*)&u.w);
        a0 += f0.x; a1 += f0.y; a2 += f1.x; a3 += f1.y;
        a4 += f2.x; a5 += f2.y; a6 += f3.x; a7 += f3.y;
    }
    float inv = 1.0f / fmaxf((float)(end - beg), 1.0f);
    uint4 o;
    __half2 h0 = __floats2half2_rn(a0 * inv, a1 * inv);
    __half2 h1 = __floats2half2_rn(a2 * inv, a3 * inv);
    __half2 h2 = __floats2half2_rn(a4 * inv, a5 * inv);
    __half2 h3 = __floats2half2_rn(a6 * inv, a7 * inv);
    o.x = *(uint32_t*)&h0; o.y = *(uint32_t*)&h1;
    o.z = *(uint32_t*)&h2; o.w = *(uint32_t*)&h3;
    *(uint4*)(g_aggh + ((size_t)c * N_ + n) * D_ + li * 8) = o;
}

// ---------------- mma.sync dual GEMM (R14: 2 CTAs/SM) ----------------
#define ASTRIDE_B 144
#define PLANE_B   18432
#define B_BYTES   (4 * PLANE_B)          // 73728
#define A_BYTES   (2 * PLANE_B)          // 36864
#define SMEM_GEMM (B_BYTES + A_BYTES)    // 110592

template <bool LAST>
__global__ void __launch_bounds__(256, 2) k_gemm(const float* __restrict__ conv_b,
                                                 int layer) {
    extern __shared__ __align__(16) char sm[];
    char* Bsm = sm;
    char* Asm = sm + B_BYTES;
    __shared__ float s_bias[128];

    const int tid = threadIdx.x;
    const int lane = tid & 31;
    const int wid = tid >> 5;
    const int wm = wid >> 2;
    const int wn = wid & 3;
    const int m0 = wm * 64, n0 = wn * 32;

    if (tid < 128) s_bias[tid] = conv_b[(size_t)layer * D_ + tid];

    // B copy: fp16 plane, pure uint4 copy (4096 slots)
    {
        const __half* Bh = g_Bh + (size_t)layer * 32768;
#pragma unroll
        for (int i = 0; i < 16; i++) {
            int slot = i * 256 + tid;
            int chunk = slot >> 10;
            int n = (slot >> 3) & 127, q = slot & 7;
            const __half* src = Bh + (size_t)n * 256 + chunk * 64 + q * 8;
            *(uint4*)(Bsm + chunk * PLANE_B + n * ASTRIDE_B + q * 16) = *(const uint4*)src;
        }
    }
    __syncthreads();

    const uint32_t a_u32 = smem_u32(Asm);
    const uint32_t b_u32 = smem_u32(Bsm);

    for (int t = blockIdx.x; t < TILES2_; t += gridDim.x) {
        const int cfg = t / NT_;
        const int nt = t - cfg * NT_;
        const int nvalid = (nt == NT_ - 1) ? (N_ - 128 * (NT_ - 1)) : 128;
        const size_t row0 = (size_t)cfg * N_ + (size_t)nt * 128;

        float acc[4][4][4];
#pragma unroll
        for (int mi = 0; mi < 4; mi++)
#pragma unroll
            for (int ni = 0; ni < 4; ni++)
#pragma unroll
                for (int q = 0; q < 4; q++) acc[mi][ni][q] = 0.f;

        uint4 av[4];
        {
#pragma unroll
            for (int i = 0; i < 4; i++) {
                int slot = i * 256 + tid;
                int n = slot >> 3, q = slot & 7;
                int nc = n < nvalid ? n : nvalid - 1;
                av[i] = *(const uint4*)(g_aggh + (row0 + nc) * 128 + q * 8);
            }
#pragma unroll
            for (int i = 0; i < 4; i++) {
                int slot = i * 256 + tid;
                int n = slot >> 3, q = slot & 7;
                *(uint4*)(Asm + n * ASTRIDE_B + q * 16) = av[i];
            }
        }
        __syncthreads();

#pragma unroll 1
        for (int s = 0; s < 4; s++) {
            if (s < 3) {
                const int koff = ((s + 1) & 1) * 64;
                const __half* srcp = ((s + 1) < 2) ? g_aggh : g_xh;
#pragma unroll
                for (int i = 0; i < 4; i++) {
                    int slot = i * 256 + tid;
                    int n = slot >> 3, q = slot & 7;
                    int nc = n < nvalid ? n : nvalid - 1;
                    av[i] = *(const uint4*)(srcp + (row0 + nc) * 128 + koff + q * 8);
                }
            }

            const uint32_t abase = a_u32 + (s & 1) * PLANE_B;
            const uint32_t bbase = b_u32 + s * PLANE_B;
#pragma unroll
            for (int ks = 0; ks < 4; ks++) {
                const int kofs = ks * 16;
                uint32_t ah[4][4], bh[4][2];
#pragma unroll
                for (int mi = 0; mi < 4; mi++) {
                    uint32_t addr = abase + (uint32_t)(m0 + mi * 16 + (lane & 15)) * ASTRIDE_B
                                  + (uint32_t)(kofs + (lane >> 4) * 8) * 2;
                    ldsm_x4(ah[mi], addr);
                }
#pragma unroll
                for (int np = 0; np < 2; np++) {
                    uint32_t addr = bbase + (uint32_t)(n0 + np * 16 + (lane & 15)) * ASTRIDE_B
                                  + (uint32_t)(kofs + (lane >> 4) * 8) * 2;
                    uint32_t bq[4];
                    ldsm_x4(bq, addr);
                    bh[np * 2][0] = bq[0]; bh[np * 2][1] = bq[2];
                    bh[np * 2 + 1][0] = bq[1]; bh[np * 2 + 1][1] = bq[3];
                }
#pragma unroll
                for (int mi = 0; mi < 4; mi++)
#pragma unroll
                    for (int ni = 0; ni < 4; ni++)
                        mma16816(acc[mi][ni], ah[mi], bh[ni]);
            }

            if (s < 3) {
                __syncthreads();
                const int b = (s + 1) & 1;
#pragma unroll
                for (int i = 0; i < 4; i++) {
                    int slot = i * 256 + tid;
                    int n = slot >> 3, q = slot & 7;
                    *(uint4*)(Asm + b * PLANE_B + n * ASTRIDE_B + q * 16) = av[i];
                }
                __syncthreads();
            }
        }

        if (!LAST) {
#pragma unroll
            for (int mi = 0; mi < 4; mi++) {
                int rr = m0 + mi * 16 + (lane >> 2);
                bool v0 = rr < nvalid, v1 = rr + 8 < nvalid;
                size_t r0 = row0 + rr;
                size_t r1 = r0 + 8;
#pragma unroll
                for (int ni = 0; ni < 4; ni++) {
                    int col = n0 + ni * 8 + (lane & 3) * 2;
                    float b0 = s_bias[col], b1 = s_bias[col + 1];
                    __half2 o0 = __floats2half2_rn(fmaxf(acc[mi][ni][0] + b0, 0.f),
                                                   fmaxf(acc[mi][ni][1] + b1, 0.f));
                    __half2 o1 = __floats2half2_rn(fmaxf(acc[mi][ni][2] + b0, 0.f),
                                                   fmaxf(acc[mi][ni][3] + b1, 0.f));
                    if (v0) *(uint32_t*)(g_xh + r0 * 128 + col) = *(uint32_t*)&o0;
                    if (v1) *(uint32_t*)(g_xh + r1 * 128 + col) = *(uint32_t*)&o1;
                }
            }
        } else {
            float p[4][2];
#pragma unroll
            for (int ni = 0; ni < 4; ni++) { p[ni][0] = 0.f; p[ni][1] = 0.f; }
#pragma unroll
            for (int mi = 0; mi < 4; mi++) {
                int rr = m0 + mi * 16 + (lane >> 2);
                float v0 = (rr < nvalid) ? 1.f : 0.f;
                float v1 = (rr + 8 < nvalid) ? 1.f : 0.f;
#pragma unroll
                for (int ni = 0; ni < 4; ni++) {
                    int col = n0 + ni * 8 + (lane & 3) * 2;
                    float b0 = s_bias[col], b1 = s_bias[col + 1];
                    p[ni][0] += v0 * fmaxf(acc[mi][ni][0] + b0, 0.f)
                              + v1 * fmaxf(acc[mi][ni][2] + b0, 0.f);
                    p[ni][1] += v0 * fmaxf(acc[mi][ni][1] + b1, 0.f)
                              + v1 * fmaxf(acc[mi][ni][3] + b1, 0.f);
                }
            }
#pragma unroll
            for (int ni = 0; ni < 4; ni++)
#pragma unroll
                for (int h = 0; h < 2; h++) {
#pragma unroll
                    for (int o = 4; o <= 16; o <<= 1)
                        p[ni][h] += __shfl_xor_sync(0xffffffffu, p[ni][h], o);
                }
            if (lane < 4) {
#pragma unroll
                for (int ni = 0; ni < 4; ni++) {
                    int col = n0 + ni * 8 + lane * 2;
                    atomicAdd(&g_pool[cfg * 128 + col], p[ni][0]);
                    atomicAdd(&g_pool[cfg * 128 + col + 1], p[ni][1]);
                }
            }
        }
        __syncthreads();
    }
}

// ---------------- MLP head ----------------
__global__ void __launch_bounds__(1024) k_mlp(
        const float* __restrict__ Wd1, const float* __restrict__ bd1,
        const float* __restrict__ Wd2, const float* __restrict__ bd2,
        const float* __restrict__ Wd3, const float* __restrict__ bd3,
        float* __restrict__ out) {
    __shared__ float sa[C_][D_];
    __shared__ float sb[C_][D_];
    int tid = threadIdx.x;
#pragma unroll
    for (int r = 0; r < 4; r++) {
        int i = r * 1024 + tid;
        sa[i >> 7][i & 127] = g_pool[i] * (1.0f / N_);
    }
    __syncthreads();
#pragma unroll
    for (int r = 0; r < 4; r++) {
        int i = r * 1024 + tid;
        int c = i >> 7, j = i & 127;
        float a = bd1[j];
#pragma unroll 8
        for (int k = 0; k < D_; k++) a += sa[c][k] * Wd1[k * D_ + j];
        sb[c][j] = fmaxf(a, 0.f);
    }
    __syncthreads();
#pragma unroll
    for (int r = 0; r < 4; r++) {
        int i = r * 1024 + tid;
        int c = i >> 7, j = i & 127;
        float a = bd2[j];
#pragma unroll 8
        for (int k = 0; k < D_; k++) a += sb[c][k] * Wd2[k * D_ + j];
        sa[c][j] = fmaxf(a, 0.f);
    }
    __syncthreads();
    if (tid < C_) {
        float a = bd3[0];
#pragma unroll 8
        for (int k = 0; k < D_; k++) a += sa[tid][k] * Wd3[k];
        out[tid] = a;
    }
}

// ---------------- launch ----------------
extern "C" void kernel_launch(void* const* d_in, const int* in_sizes, int n_in,
                              void* d_out, int out_size) {
    (void)n_in; (void)out_size;
    const float* x_node_cfg      = (const float*)d_in[0];
    const float* x_feat          = (const float*)d_in[1];
    const int*   x_op            = (const int*)d_in[2];
    const int*   edge_index      = (const int*)d_in[3];
    const int*   node_config_ids = (const int*)d_in[4];
    const float* emb_table       = (const float*)d_in[5];
    const float* W_lin           = (const float*)d_in[6];
    const float* b_lin           = (const float*)d_in[7];
    const float* conv_Wl         = (const float*)d_in[8];
    const float* conv_Wr         = (const float*)d_in[9];
    const float* conv_b          = (const float*)d_in[10];
    const float* Wd1             = (const float*)d_in[11];
    const float* bd1             = (const float*)d_in[12];
    const float* Wd2             = (const float*)d_in[13];
    const float* bd2             = (const float*)d_in[14];
    const float* Wd3             = (const float*)d_in[15];
    const float* bd3             = (const float*)d_in[16];
    float* out = (float*)d_out;

    int E = in_sizes[3] / 2;
    const int* e_src = edge_index;
    const int* e_dst = edge_index + E;

    cudaFuncSetAttribute(k_gemm<false>, cudaFuncAttributeMaxDynamicSharedMemorySize, SMEM_GEMM);
    cudaFuncSetAttribute(k_gemm<true>,  cudaFuncAttributeMaxDynamicSharedMemorySize, SMEM_GEMM);

    int cntBlocks = (E + 127) / 128;
    k_count_base<<<625 + cntBlocks, 128>>>(x_feat, x_op, emb_table, W_lin, b_lin, e_dst, E);
    k_scan_bcast_wt<<<1 + 10000 + 128, 1024>>>(conv_Wl, conv_Wr);
    k_correct_fill<<<NC_ + (E + 255) / 256, 256>>>(x_node_cfg, node_config_ids, W_lin,
                                                   e_src, e_dst, E);

    for (int l = 0; l < L_; l++) {
        k_prop<<<((C_ / 2) * N_) / 8, 256>>>();
        if (l < L_ - 1)
            k_gemm<false><<<GEMM_CTAS, 256, SMEM_GEMM>>>(conv_b, l);
        else
            k_gemm<true><<<GEMM_CTAS, 256, SMEM_GEMM>>>(conv_b, l);
    }

    k_mlp<<<1, 1024>>>(Wd1, bd1, Wd2, bd2, Wd3, bd3, out);
}